// round 13
// baseline (speedup 1.0000x reference)
#include <cuda_runtime.h>
#include <math_constants.h>

#define EMB 768
#define DK  256
#define DV  256
#define BATCH 8
#define SEQ 2048
#define NHEAD 3

// ---------------- scratch (device globals; no allocation in kernel_launch) ----
__device__ float g_x [(size_t)BATCH * SEQ * EMB];          // tf32-rounded x
__device__ float g_Wq[(size_t)NHEAD * EMB * DK];
__device__ float g_Wk[(size_t)NHEAD * EMB * DK];
__device__ float g_Wv[(size_t)NHEAD * EMB * DV];
__device__ float g_W0[(size_t)(NHEAD * DV) * EMB];
__device__ float g_Q [(size_t)BATCH * NHEAD * SEQ * DK];   // [b,h,n,d]
__device__ float g_K [(size_t)BATCH * NHEAD * SEQ * DK];
__device__ float g_KT[(size_t)BATCH * NHEAD * DK * SEQ];   // [b,h,d,n]
__device__ float g_V [(size_t)BATCH * NHEAD * SEQ * DV];
__device__ float g_C [(size_t)BATCH * SEQ * (NHEAD * DV)]; // concat context

// round fp32 -> tf32 (RN); result is fp32 bit-pattern valid as tf32 operand
__device__ __forceinline__ float to_tf32(float f) {
    unsigned u;
    asm("cvt.rna.tf32.f32 %0, %1;" : "=r"(u) : "f"(f));
    return __uint_as_float(u);
}

__device__ __forceinline__ void cp16(float* dst_smem, const float* src) {
    unsigned d = (unsigned)__cvta_generic_to_shared(dst_smem);
    asm volatile("cp.async.cg.shared.global [%0], [%1], 16;" :: "r"(d), "l"(src));
}
__device__ __forceinline__ void cp_commit() {
    asm volatile("cp.async.commit_group;");
}
template<int N>
__device__ __forceinline__ void cp_wait() {
    asm volatile("cp.async.wait_group %0;" :: "n"(N));
}

#define MMA_TF32(acc, a, b0, b1)                                              \
    asm volatile(                                                             \
        "mma.sync.aligned.m16n8k8.row.col.f32.tf32.tf32.f32 "                 \
        "{%0,%1,%2,%3}, {%4,%5,%6,%7}, {%8,%9}, {%0,%1,%2,%3};"               \
        : "+f"((acc)[0]), "+f"((acc)[1]), "+f"((acc)[2]), "+f"((acc)[3])      \
        : "r"((a)[0]), "r"((a)[1]), "r"((a)[2]), "r"((a)[3]),                 \
          "r"(b0), "r"(b1))

// ---------------- generic GEMM smem geometry (qkv / proj) --------------------
#define A_STRIDE 20
#define B_STRIDE 136
#define A_STG (128 * A_STRIDE)      // 2560
#define B_STG (16 * B_STRIDE)       // 2176
#define STG   (A_STG + B_STG)       // 4736 floats
#define SMEM_BYTES (3 * STG * 4)    // 56832 B

// ---------------- fused attention smem geometry (floats) ---------------------
#define P_STRIDE 132
#define AT_P_OFF 0                                  // P: 128 x 132
#define AT_Q_OFF (128 * P_STRIDE)                   // 16896; Q: 3 x 128x20
#define AT_K_OFF (AT_Q_OFF + 3 * A_STG)             // 24576; KT: 3 x 16x136
#define AT_V_OFF (AT_K_OFF + 3 * B_STG)             // 31104; V: 3 x 16x264
#define V_STRIDE 264
#define V_STG (16 * V_STRIDE)                       // 4224
#define AT_RS_OFF (AT_V_OFF + 3 * V_STG)            // 43776; rs: 4 x 132
#define ATTN_SMEM_FLOATS (AT_RS_OFF + 4 * P_STRIDE) // 44304
#define ATTN_SMEM_BYTES (ATTN_SMEM_FLOATS * 4)      // 177216 B

// =============================================================================
// tf32 warp-MMA GEMM (NN), cp.async 3-stage pipeline, ONE barrier per k-tile.
// CTA tile 128x128, BK=16, 128 threads = 4 warps (2x2), warp tile 64x64.
// (unchanged from R7/R11 — used for qkv + proj)
// =============================================================================
template<bool ROUND>
__device__ __forceinline__ void mma_gemm(
    const float* __restrict__ A, int lda,
    const float* __restrict__ B, int ldb,
    float*       __restrict__ C, int ldc,
    int K, float alpha, const float* __restrict__ bias)
{
    extern __shared__ float smem[];

    const int tid  = threadIdx.x;
    const int lane = tid & 31;
    const int warp = tid >> 5;
    const int wm   = warp >> 1;
    const int wn   = warp & 1;
    const long m0  = (long)blockIdx.x * 128;
    const long n0  = (long)blockIdx.y * 128;

    auto load_stage = [&](int st, int k0) {
        float* As = smem + st * STG;
        float* Bs = As + A_STG;
#pragma unroll
        for (int i = 0; i < 4; i++) {
            const int r  = i * 32 + (tid >> 2);
            const int c4 = (tid & 3) << 2;
            cp16(&As[r * A_STRIDE + c4], A + (m0 + r) * (long)lda + k0 + c4);
        }
#pragma unroll
        for (int i = 0; i < 4; i++) {
            const int idx = i * 128 + tid;
            const int k   = idx >> 5;
            const int n4  = (idx & 31) << 2;
            cp16(&Bs[k * B_STRIDE + n4], B + (long)(k0 + k) * ldb + n0 + n4);
        }
    };

    float acc[4][8][4];
#pragma unroll
    for (int mt = 0; mt < 4; mt++)
#pragma unroll
        for (int nt = 0; nt < 8; nt++)
#pragma unroll
            for (int q = 0; q < 4; q++) acc[mt][nt][q] = 0.0f;

    const int KT = K >> 4;
    load_stage(0, 0);  cp_commit();
    load_stage(1, 16); cp_commit();

    for (int kt = 0; kt < KT; kt++) {
        cp_wait<1>();
        __syncthreads();

        if (kt + 2 < KT) load_stage((kt + 2) % 3, (kt + 2) << 4);
        cp_commit();

        const float* As = smem + (kt % 3) * STG;
        const float* Bs = As + A_STG;
#pragma unroll
        for (int kk = 0; kk < 16; kk += 8) {
            unsigned a[4][4];
#pragma unroll
            for (int mt = 0; mt < 4; mt++) {
                const int r = wm * 64 + mt * 16 + (lane >> 2);
                const int c = kk + (lane & 3);
                a[mt][0] = __float_as_uint(As[r * A_STRIDE + c]);
                a[mt][1] = __float_as_uint(As[(r + 8) * A_STRIDE + c]);
                a[mt][2] = __float_as_uint(As[r * A_STRIDE + c + 4]);
                a[mt][3] = __float_as_uint(As[(r + 8) * A_STRIDE + c + 4]);
            }
#pragma unroll
            for (int nt = 0; nt < 8; nt++) {
                const int nc = wn * 64 + nt * 8 + (lane >> 2);
                unsigned b0 = __float_as_uint(Bs[(kk + (lane & 3)) * B_STRIDE + nc]);
                unsigned b1 = __float_as_uint(Bs[(kk + 4 + (lane & 3)) * B_STRIDE + nc]);
#pragma unroll
                for (int mt = 0; mt < 4; mt++) MMA_TF32(acc[mt][nt], a[mt], b0, b1);
            }
        }
    }

#pragma unroll
    for (int mt = 0; mt < 4; mt++) {
        const long r = m0 + wm * 64 + mt * 16 + (lane >> 2);
#pragma unroll
        for (int nt = 0; nt < 8; nt++) {
            const long col = n0 + wn * 64 + nt * 8 + ((lane & 3) << 1);
            float bx = 0.f, by = 0.f;
            if (bias) { bx = bias[col]; by = bias[col + 1]; }
            float v0 = acc[mt][nt][0] * alpha + bx;
            float v1 = acc[mt][nt][1] * alpha + by;
            float v2 = acc[mt][nt][2] * alpha + bx;
            float v3 = acc[mt][nt][3] * alpha + by;
            if (ROUND) { v0 = to_tf32(v0); v1 = to_tf32(v1); v2 = to_tf32(v2); v3 = to_tf32(v3); }
            *(float2*)(C + r * ldc + col)       = make_float2(v0, v1);
            *(float2*)(C + (r + 8) * ldc + col) = make_float2(v2, v3);
        }
    }
}

// =============================================================================
// FUSED ATTENTION: out[128, 256] = softmax(Q @ K^T / 16) @ V for one
// (batch,head) and one 128-row Q block. No S materialization in gmem.
// 256 threads = 8 warps (2x4). 16 KV tiles of 128 keys.
// Per tile: phase1 S=Q@KT (3-stage cp.async, warp tile 64x32),
//           phase2 P=tf32(exp(S/16-8)) -> smem + rowsum partials,
//           phase3 O += P@V (V 3-stage cp.async, warp tile 64x64).
// One commit group per iteration everywhere -> wait<1> FIFO stays exact;
// V0/V1 prefetched in phase1 tail, next tile's QK in phase3 tail.
// Epilogue divides by reduced rowsums (fixed-shift exp, R11-validated).
// =============================================================================
__global__ void __launch_bounds__(256, 1) attn_kernel()
{
    extern __shared__ float smem[];
    float* Pm = smem + AT_P_OFF;
    float* rs = smem + AT_RS_OFF;

    const int tid  = threadIdx.x;
    const int lane = tid & 31;
    const int warp = tid >> 5;
    const int wm   = warp >> 2;      // 0..1 (64 rows)
    const int wn   = warp & 3;       // 0..3
    const int p    = blockIdx.z;
    const int b    = p / NHEAD, h = p % NHEAD;
    const long m0  = (long)blockIdx.x * 128;

    const float* Qp  = g_Q  + (size_t)p * SEQ * DK;
    const float* KTp = g_KT + (size_t)p * DK * SEQ;
    const float* Vp  = g_V  + (size_t)p * SEQ * DV;

    auto loadQK = [&](int t, int kt) {        // stage kt%3
        float* Qs = smem + AT_Q_OFF + (kt % 3) * A_STG;
        float* Ks = smem + AT_K_OFF + (kt % 3) * B_STG;
#pragma unroll
        for (int i = 0; i < 2; i++) {         // Q: 128 rows x 16 d
            const int idx = i * 256 + tid;
            const int r = idx >> 2, c4 = (idx & 3) << 2;
            cp16(&Qs[r * A_STRIDE + c4], Qp + (m0 + r) * DK + kt * 16 + c4);
        }
#pragma unroll
        for (int i = 0; i < 2; i++) {         // KT: 16 d x 128 keys
            const int idx = i * 256 + tid;
            const int k = idx >> 5, n4 = (idx & 31) << 2;
            cp16(&Ks[k * B_STRIDE + n4], KTp + (size_t)(kt * 16 + k) * SEQ + t * 128 + n4);
        }
    };
    auto loadV = [&](int t, int vt) {         // stage vt%3
        float* Vs = smem + AT_V_OFF + (vt % 3) * V_STG;
#pragma unroll
        for (int i = 0; i < 4; i++) {         // V: 16 keys x 256 dv
            const int idx = i * 256 + tid;
            const int k = idx >> 6, n4 = (idx & 63) << 2;
            cp16(&Vs[k * V_STRIDE + n4], Vp + (size_t)(t * 128 + vt * 16 + k) * DV + n4);
        }
    };

    float oacc[4][8][4];
#pragma unroll
    for (int mt = 0; mt < 4; mt++)
#pragma unroll
        for (int nt = 0; nt < 8; nt++)
#pragma unroll
            for (int q = 0; q < 4; q++) oacc[mt][nt][q] = 0.0f;

    float ps[4][2];                            // rowsum partials (rows r, r+8)
#pragma unroll
    for (int mt = 0; mt < 4; mt++) { ps[mt][0] = 0.f; ps[mt][1] = 0.f; }

    loadQK(0, 0); cp_commit();
    loadQK(0, 1); cp_commit();

    for (int t = 0; t < 16; t++) {
        // ---------------- phase 1: S = Q @ KT (d-loop, 16 iters) -------------
        float sacc[4][4][4];
#pragma unroll
        for (int mt = 0; mt < 4; mt++)
#pragma unroll
            for (int nt = 0; nt < 4; nt++)
#pragma unroll
                for (int q = 0; q < 4; q++) sacc[mt][nt][q] = 0.0f;

        for (int kt = 0; kt < 16; kt++) {
            cp_wait<1>();
            __syncthreads();

            if (kt < 14)       loadQK(t, kt + 2);
            else if (kt == 14) loadV(t, 0);
            else               loadV(t, 1);
            cp_commit();

            const float* Qs = smem + AT_Q_OFF + (kt % 3) * A_STG;
            const float* Ks = smem + AT_K_OFF + (kt % 3) * B_STG;
#pragma unroll
            for (int kk = 0; kk < 16; kk += 8) {
                unsigned a[4][4];
#pragma unroll
                for (int mt = 0; mt < 4; mt++) {
                    const int r = wm * 64 + mt * 16 + (lane >> 2);
                    const int c = kk + (lane & 3);
                    a[mt][0] = __float_as_uint(Qs[r * A_STRIDE + c]);
                    a[mt][1] = __float_as_uint(Qs[(r + 8) * A_STRIDE + c]);
                    a[mt][2] = __float_as_uint(Qs[r * A_STRIDE + c + 4]);
                    a[mt][3] = __float_as_uint(Qs[(r + 8) * A_STRIDE + c + 4]);
                }
#pragma unroll
                for (int nt = 0; nt < 4; nt++) {
                    const int nc = wn * 32 + nt * 8 + (lane >> 2);
                    unsigned b0 = __float_as_uint(Ks[(kk + (lane & 3)) * B_STRIDE + nc]);
                    unsigned b1 = __float_as_uint(Ks[(kk + 4 + (lane & 3)) * B_STRIDE + nc]);
#pragma unroll
                    for (int mt = 0; mt < 4; mt++) MMA_TF32(sacc[mt][nt], a[mt], b0, b1);
                }
            }
        }

        // ---------------- phase 2: P = tf32(exp(S/16 - 8)) -> smem -----------
        // (all warps have passed >=1 barrier since any prior read of Pm)
#pragma unroll
        for (int mt = 0; mt < 4; mt++) {
            const int r = wm * 64 + mt * 16 + (lane >> 2);
#pragma unroll
            for (int nt = 0; nt < 4; nt++) {
                const int nc = wn * 32 + nt * 8 + ((lane & 3) << 1);
                float e0 = to_tf32(__expf(fmaf(sacc[mt][nt][0], 0.0625f, -8.0f)));
                float e1 = to_tf32(__expf(fmaf(sacc[mt][nt][1], 0.0625f, -8.0f)));
                float e2 = to_tf32(__expf(fmaf(sacc[mt][nt][2], 0.0625f, -8.0f)));
                float e3 = to_tf32(__expf(fmaf(sacc[mt][nt][3], 0.0625f, -8.0f)));
                ps[mt][0] += e0 + e1;
                ps[mt][1] += e2 + e3;
                *(float2*)&Pm[r * P_STRIDE + nc]       = make_float2(e0, e1);
                *(float2*)&Pm[(r + 8) * P_STRIDE + nc] = make_float2(e2, e3);
            }
        }
        __syncthreads();                       // P visible to all warps

        // ---------------- phase 3: O += P @ V (key-loop, 8 iters) ------------
        for (int vt = 0; vt < 8; vt++) {
            cp_wait<1>();
            __syncthreads();

            if (vt < 6)        loadV(t, vt + 2);
            else if (t < 15) { if (vt == 6) loadQK(t + 1, 0); else loadQK(t + 1, 1); }
            cp_commit();

            const float* Vs = smem + AT_V_OFF + (vt % 3) * V_STG;
#pragma unroll
            for (int kk = 0; kk < 16; kk += 8) {
                unsigned a[4][4];
#pragma unroll
                for (int mt = 0; mt < 4; mt++) {
                    const int r = wm * 64 + mt * 16 + (lane >> 2);
                    const int c = vt * 16 + kk + (lane & 3);
                    a[mt][0] = __float_as_uint(Pm[r * P_STRIDE + c]);
                    a[mt][1] = __float_as_uint(Pm[(r + 8) * P_STRIDE + c]);
                    a[mt][2] = __float_as_uint(Pm[r * P_STRIDE + c + 4]);
                    a[mt][3] = __float_as_uint(Pm[(r + 8) * P_STRIDE + c + 4]);
                }
#pragma unroll
                for (int nt = 0; nt < 8; nt++) {
                    const int nc = wn * 64 + nt * 8 + (lane >> 2);
                    unsigned b0 = __float_as_uint(Vs[(kk + (lane & 3)) * V_STRIDE + nc]);
                    unsigned b1 = __float_as_uint(Vs[(kk + 4 + (lane & 3)) * V_STRIDE + nc]);
#pragma unroll
                    for (int mt = 0; mt < 4; mt++) MMA_TF32(oacc[mt][nt], a[mt], b0, b1);
                }
            }
        }
    }

    // ---------------- rowsum reduction + epilogue -----------------------------
#pragma unroll
    for (int mt = 0; mt < 4; mt++)
#pragma unroll
        for (int hh = 0; hh < 2; hh++) {
            float v = ps[mt][hh];
            v += __shfl_xor_sync(0xffffffffu, v, 1);
            v += __shfl_xor_sync(0xffffffffu, v, 2);
            ps[mt][hh] = v;                      // per-warp 32-col rowsum
        }
    if ((lane & 3) == 0) {
#pragma unroll
        for (int mt = 0; mt < 4; mt++)
#pragma unroll
            for (int hh = 0; hh < 2; hh++) {
                const int r = wm * 64 + mt * 16 + (lane >> 2) + hh * 8;
                rs[wn * P_STRIDE + r] = ps[mt][hh];
            }
    }
    __syncthreads();

    float* Cp = g_C + ((size_t)b * SEQ + m0) * (NHEAD * DV) + h * DV;
#pragma unroll
    for (int mt = 0; mt < 4; mt++) {
        const int r0 = wm * 64 + mt * 16 + (lane >> 2);
        const int r1 = r0 + 8;
        const float inv0 = 1.0f / (rs[r0] + rs[P_STRIDE + r0] +
                                   rs[2 * P_STRIDE + r0] + rs[3 * P_STRIDE + r0]);
        const float inv1 = 1.0f / (rs[r1] + rs[P_STRIDE + r1] +
                                   rs[2 * P_STRIDE + r1] + rs[3 * P_STRIDE + r1]);
#pragma unroll
        for (int nt = 0; nt < 8; nt++) {
            const int col = wn * 64 + nt * 8 + ((lane & 3) << 1);
            float v0 = to_tf32(oacc[mt][nt][0] * inv0);
            float v1 = to_tf32(oacc[mt][nt][1] * inv0);
            float v2 = to_tf32(oacc[mt][nt][2] * inv1);
            float v3 = to_tf32(oacc[mt][nt][3] * inv1);
            *(float2*)(Cp + (size_t)r0 * (NHEAD * DV) + col) = make_float2(v0, v1);
            *(float2*)(Cp + (size_t)r1 * (NHEAD * DV) + col) = make_float2(v2, v3);
        }
    }
}

// ---------------- prepass: round inputs to tf32 -------------------------------
__global__ void __launch_bounds__(256) round_x_kernel(const float* __restrict__ x)
{
    const size_t n = (size_t)BATCH * SEQ * EMB;
    for (size_t i = (size_t)blockIdx.x * 256 + threadIdx.x; i < n; i += (size_t)gridDim.x * 256)
        g_x[i] = to_tf32(x[i]);
}
__global__ void __launch_bounds__(256) round_w_kernel(
    const float* __restrict__ Wq, const float* __restrict__ Wk,
    const float* __restrict__ Wv, const float* __restrict__ W0)
{
    const size_t n = (size_t)NHEAD * EMB * DK;   // == 768*768 for W0 too
    for (size_t i = (size_t)blockIdx.x * 256 + threadIdx.x; i < n; i += (size_t)gridDim.x * 256) {
        g_Wq[i] = to_tf32(Wq[i]);
        g_Wk[i] = to_tf32(Wk[i]);
        g_Wv[i] = to_tf32(Wv[i]);
        g_W0[i] = to_tf32(W0[i]);
    }
}

// ---------------- K transpose: g_K [p][n][d] -> g_KT [p][d][n] ----------------
__global__ void __launch_bounds__(256) transpose_k_kernel()
{
    __shared__ float tile[32][33];
    const int p  = blockIdx.z;
    const int nB = blockIdx.x * 32;
    const int dB = blockIdx.y * 32;
    const int tx = threadIdx.x & 31;
    const int ty = threadIdx.x >> 5;
    const float* src = g_K  + (size_t)p * SEQ * DK;
    float*       dst = g_KT + (size_t)p * DK * SEQ;
#pragma unroll
    for (int j = 0; j < 4; j++)
        tile[ty + j * 8][tx] = src[(size_t)(nB + ty + j * 8) * DK + dB + tx];
    __syncthreads();
#pragma unroll
    for (int j = 0; j < 4; j++)
        dst[(size_t)(dB + ty + j * 8) * SEQ + nB + tx] = tile[tx][ty + j * 8];
}

// ---------------- stage kernels ----------------------------------------------
__global__ void __launch_bounds__(128, 2) qkv_kernel(
    const float* __restrict__ bq, const float* __restrict__ bk,
    const float* __restrict__ bv)
{
    const int z = blockIdx.z;
    const int b = z / 9, r = z % 9;
    const int mat = r / 3, h = r % 3;
    const float* A    = g_x + (size_t)b * SEQ * EMB;
    const float* W    = (mat == 0 ? g_Wq : (mat == 1 ? g_Wk : g_Wv)) + (size_t)h * EMB * DK;
    const float* bias = (mat == 0 ? bq : (mat == 1 ? bk : bv)) + h * DK;
    float* C = (mat == 0 ? g_Q : (mat == 1 ? g_K : g_V)) + (size_t)(b * NHEAD + h) * SEQ * DK;
    mma_gemm<true>(A, EMB, W, DK, C, DK, EMB, 1.0f, bias);
}

__global__ void __launch_bounds__(128, 2) proj_kernel(
    const float* __restrict__ b0, float* __restrict__ out)
{
    mma_gemm<false>(g_C, NHEAD * DV, g_W0, EMB, out, EMB, NHEAD * DV, 1.0f, b0);
}

// ---------------- launch ------------------------------------------------------
extern "C" void kernel_launch(void* const* d_in, const int* in_sizes, int n_in,
                              void* d_out, int out_size)
{
    const float* x  = (const float*)d_in[0];
    const float* Wq = (const float*)d_in[1];
    const float* bq = (const float*)d_in[2];
    const float* Wk = (const float*)d_in[3];
    const float* bk = (const float*)d_in[4];
    const float* Wv = (const float*)d_in[5];
    const float* bv = (const float*)d_in[6];
    const float* W0 = (const float*)d_in[7];
    const float* b0 = (const float*)d_in[8];
    float* out = (float*)d_out;

    static bool attr_done = false;
    if (!attr_done) {
        cudaFuncSetAttribute(qkv_kernel,  cudaFuncAttributeMaxDynamicSharedMemorySize, SMEM_BYTES);
        cudaFuncSetAttribute(attn_kernel, cudaFuncAttributeMaxDynamicSharedMemorySize, ATTN_SMEM_BYTES);
        cudaFuncSetAttribute(proj_kernel, cudaFuncAttributeMaxDynamicSharedMemorySize, SMEM_BYTES);
        attr_done = true;
    }

    round_x_kernel<<<2048, 256>>>(x);
    round_w_kernel<<<512, 256>>>(Wq, Wk, Wv, W0);

    dim3 g1(SEQ / 128, DK / 128, BATCH * 9);
    qkv_kernel<<<g1, 128, SMEM_BYTES>>>(bq, bk, bv);

    dim3 gt(SEQ / 32, DK / 32, BATCH * NHEAD);
    transpose_k_kernel<<<gt, 256>>>();

    dim3 ga(SEQ / 128, 1, BATCH * NHEAD);
    attn_kernel<<<ga, 256, ATTN_SMEM_BYTES>>>();

    dim3 g5(BATCH * SEQ / 128, EMB / 128);
    proj_kernel<<<g5, 128, SMEM_BYTES>>>(b0, out);
}

// round 14
// speedup vs baseline: 1.0861x; 1.0861x over previous
#include <cuda_runtime.h>
#include <math_constants.h>

#define EMB 768
#define DK  256
#define DV  256
#define BATCH 8
#define SEQ 2048
#define NHEAD 3

// ---------------- scratch (device globals; no allocation in kernel_launch) ----
__device__ float g_x [(size_t)BATCH * SEQ * EMB];          // tf32-rounded x
__device__ float g_Wq[(size_t)NHEAD * EMB * DK];
__device__ float g_Wk[(size_t)NHEAD * EMB * DK];
__device__ float g_Wv[(size_t)NHEAD * EMB * DV];
__device__ float g_W0[(size_t)(NHEAD * DV) * EMB];
__device__ float g_Q [(size_t)BATCH * NHEAD * SEQ * DK];   // [b,h,n,d]
__device__ float g_K [(size_t)BATCH * NHEAD * SEQ * DK];
__device__ float g_KT[(size_t)BATCH * NHEAD * DK * SEQ];   // [b,h,d,n]
__device__ float g_V [(size_t)BATCH * NHEAD * SEQ * DV];
__device__ float g_S [(size_t)BATCH * NHEAD * SEQ * SEQ];  // P = exp(s/16-8)
__device__ float g_pr[(size_t)BATCH * NHEAD * 16 * SEQ];   // partial rowsums
__device__ float g_inv[(size_t)BATCH * NHEAD * SEQ];       // 1 / rowsum
__device__ float g_C [(size_t)BATCH * SEQ * (NHEAD * DV)]; // concat context

// round fp32 -> tf32 (RN); result is fp32 bit-pattern valid as tf32 operand
__device__ __forceinline__ float to_tf32(float f) {
    unsigned u;
    asm("cvt.rna.tf32.f32 %0, %1;" : "=r"(u) : "f"(f));
    return __uint_as_float(u);
}

__device__ __forceinline__ void cp16(float* dst_smem, const float* src) {
    unsigned d = (unsigned)__cvta_generic_to_shared(dst_smem);
    asm volatile("cp.async.cg.shared.global [%0], [%1], 16;" :: "r"(d), "l"(src));
}
__device__ __forceinline__ void cp_commit() {
    asm volatile("cp.async.commit_group;");
}
template<int N>
__device__ __forceinline__ void cp_wait() {
    asm volatile("cp.async.wait_group %0;" :: "n"(N));
}

#define MMA_TF32(acc, a, b0, b1)                                              \
    asm volatile(                                                             \
        "mma.sync.aligned.m16n8k8.row.col.f32.tf32.tf32.f32 "                 \
        "{%0,%1,%2,%3}, {%4,%5,%6,%7}, {%8,%9}, {%0,%1,%2,%3};"               \
        : "+f"((acc)[0]), "+f"((acc)[1]), "+f"((acc)[2]), "+f"((acc)[3])      \
        : "r"((a)[0]), "r"((a)[1]), "r"((a)[2]), "r"((a)[3]),                 \
          "r"(b0), "r"(b1))

// smem stage geometry (floats)
#define A_STRIDE 20
#define B_STRIDE 136
#define A_STG (128 * A_STRIDE)      // 2560
#define B_STG (16 * B_STRIDE)       // 2176
#define STG   (A_STG + B_STG)       // 4736 floats
#define SMEM_BYTES (3 * STG * 4)    // 56832 B

// =============================================================================
// tf32 warp-MMA GEMM (NN), cp.async 3-stage pipeline, ONE barrier per k-tile.
// CTA tile 128x128, BK=16, 128 threads = 4 warps (2x2), warp tile 64x64.
// EMODE 0: C = acc*alpha + bias                       (proj)
// EMODE 1: C = tf32(acc*alpha + bias)                 (qkv)
// EMODE 2: C = tf32(exp(acc*alpha - 8)); partial rowsums -> pr_out[m0+r] (scores)
// EMODE 3: C = tf32(acc * inv[m0+r])                  (av)
// =============================================================================
template<int EMODE>
__device__ __forceinline__ void mma_gemm(
    const float* __restrict__ A, int lda,
    const float* __restrict__ B, int ldb,
    float*       __restrict__ C, int ldc,
    int K, float alpha, const float* __restrict__ bias,
    float* __restrict__ pr_out, const float* __restrict__ inv)
{
    extern __shared__ float smem[];

    const int tid  = threadIdx.x;
    const int lane = tid & 31;
    const int warp = tid >> 5;
    const int wm   = warp >> 1;      // 0..1 (64 rows each)
    const int wn   = warp & 1;       // 0..1 (64 cols each)
    const long m0  = (long)blockIdx.x * 128;
    const long n0  = (long)blockIdx.y * 128;

    auto load_stage = [&](int st, int k0) {
        float* As = smem + st * STG;
        float* Bs = As + A_STG;
#pragma unroll
        for (int i = 0; i < 4; i++) {       // A: 128 rows x 16 k
            const int r  = i * 32 + (tid >> 2);
            const int c4 = (tid & 3) << 2;
            cp16(&As[r * A_STRIDE + c4], A + (m0 + r) * (long)lda + k0 + c4);
        }
#pragma unroll
        for (int i = 0; i < 4; i++) {       // B: 16 k x 128 n
            const int idx = i * 128 + tid;
            const int k   = idx >> 5;
            const int n4  = (idx & 31) << 2;
            cp16(&Bs[k * B_STRIDE + n4], B + (long)(k0 + k) * ldb + n0 + n4);
        }
    };

    float acc[4][8][4];
#pragma unroll
    for (int mt = 0; mt < 4; mt++)
#pragma unroll
        for (int nt = 0; nt < 8; nt++)
#pragma unroll
            for (int q = 0; q < 4; q++) acc[mt][nt][q] = 0.0f;

    const int KT = K >> 4;
    load_stage(0, 0);  cp_commit();
    load_stage(1, 16); cp_commit();

    for (int kt = 0; kt < KT; kt++) {
        cp_wait<1>();
        __syncthreads();

        if (kt + 2 < KT) load_stage((kt + 2) % 3, (kt + 2) << 4);
        cp_commit();

        const float* As = smem + (kt % 3) * STG;
        const float* Bs = As + A_STG;
#pragma unroll
        for (int kk = 0; kk < 16; kk += 8) {
            unsigned a[4][4];
#pragma unroll
            for (int mt = 0; mt < 4; mt++) {
                const int r = wm * 64 + mt * 16 + (lane >> 2);
                const int c = kk + (lane & 3);
                a[mt][0] = __float_as_uint(As[r * A_STRIDE + c]);
                a[mt][1] = __float_as_uint(As[(r + 8) * A_STRIDE + c]);
                a[mt][2] = __float_as_uint(As[r * A_STRIDE + c + 4]);
                a[mt][3] = __float_as_uint(As[(r + 8) * A_STRIDE + c + 4]);
            }
#pragma unroll
            for (int nt = 0; nt < 8; nt++) {
                const int nc = wn * 64 + nt * 8 + (lane >> 2);
                unsigned b0 = __float_as_uint(Bs[(kk + (lane & 3)) * B_STRIDE + nc]);
                unsigned b1 = __float_as_uint(Bs[(kk + 4 + (lane & 3)) * B_STRIDE + nc]);
#pragma unroll
                for (int mt = 0; mt < 4; mt++) MMA_TF32(acc[mt][nt], a[mt], b0, b1);
            }
        }
    }

    // ---- epilogue ----
    if (EMODE == 2) {
        // P = tf32(exp(acc*alpha - 8)) + deterministic partial rowsums
        float psum[4][2];
#pragma unroll
        for (int mt = 0; mt < 4; mt++) { psum[mt][0] = 0.f; psum[mt][1] = 0.f; }
#pragma unroll
        for (int mt = 0; mt < 4; mt++) {
            const long r = m0 + wm * 64 + mt * 16 + (lane >> 2);
#pragma unroll
            for (int nt = 0; nt < 8; nt++) {
                const long col = n0 + wn * 64 + nt * 8 + ((lane & 3) << 1);
                float e0 = to_tf32(__expf(fmaf(acc[mt][nt][0], alpha, -8.0f)));
                float e1 = to_tf32(__expf(fmaf(acc[mt][nt][1], alpha, -8.0f)));
                float e2 = to_tf32(__expf(fmaf(acc[mt][nt][2], alpha, -8.0f)));
                float e3 = to_tf32(__expf(fmaf(acc[mt][nt][3], alpha, -8.0f)));
                psum[mt][0] += e0 + e1;
                psum[mt][1] += e2 + e3;
                *(float2*)(C + r * ldc + col)       = make_float2(e0, e1);
                *(float2*)(C + (r + 8) * ldc + col) = make_float2(e2, e3);
            }
        }
        __syncthreads();                 // all warps done with stage smem
        float* rs = smem;                // 2 x 128 floats
#pragma unroll
        for (int mt = 0; mt < 4; mt++)
#pragma unroll
            for (int hh = 0; hh < 2; hh++) {
                float v = psum[mt][hh];
                v += __shfl_xor_sync(0xffffffffu, v, 1);
                v += __shfl_xor_sync(0xffffffffu, v, 2);
                if ((lane & 3) == 0)
                    rs[wn * 128 + wm * 64 + mt * 16 + (lane >> 2) + hh * 8] = v;
            }
        __syncthreads();
        if (tid < 128) pr_out[m0 + tid] = rs[tid] + rs[128 + tid];
        return;
    }

#pragma unroll
    for (int mt = 0; mt < 4; mt++) {
        const int  rl = wm * 64 + mt * 16 + (lane >> 2);
        const long r  = m0 + rl;
        float i0 = 1.f, i1 = 1.f;
        if (EMODE == 3) { i0 = inv[m0 + rl]; i1 = inv[m0 + rl + 8]; }
#pragma unroll
        for (int nt = 0; nt < 8; nt++) {
            const long col = n0 + wn * 64 + nt * 8 + ((lane & 3) << 1);
            float v0, v1, v2, v3;
            if (EMODE == 3) {
                v0 = to_tf32(acc[mt][nt][0] * i0);
                v1 = to_tf32(acc[mt][nt][1] * i0);
                v2 = to_tf32(acc[mt][nt][2] * i1);
                v3 = to_tf32(acc[mt][nt][3] * i1);
            } else {
                float bx = 0.f, by = 0.f;
                if (bias) { bx = bias[col]; by = bias[col + 1]; }
                v0 = acc[mt][nt][0] * alpha + bx;
                v1 = acc[mt][nt][1] * alpha + by;
                v2 = acc[mt][nt][2] * alpha + bx;
                v3 = acc[mt][nt][3] * alpha + by;
                if (EMODE == 1) { v0 = to_tf32(v0); v1 = to_tf32(v1);
                                  v2 = to_tf32(v2); v3 = to_tf32(v3); }
            }
            *(float2*)(C + r * ldc + col)       = make_float2(v0, v1);
            *(float2*)(C + (r + 8) * ldc + col) = make_float2(v2, v3);
        }
    }
}

// ---------------- prepass: round inputs to tf32 -------------------------------
__global__ void __launch_bounds__(256) round_x_kernel(const float* __restrict__ x)
{
    const size_t n = (size_t)BATCH * SEQ * EMB;
    for (size_t i = (size_t)blockIdx.x * 256 + threadIdx.x; i < n; i += (size_t)gridDim.x * 256)
        g_x[i] = to_tf32(x[i]);
}
__global__ void __launch_bounds__(256) round_w_kernel(
    const float* __restrict__ Wq, const float* __restrict__ Wk,
    const float* __restrict__ Wv, const float* __restrict__ W0)
{
    const size_t n = (size_t)NHEAD * EMB * DK;   // == 768*768 for W0 too
    for (size_t i = (size_t)blockIdx.x * 256 + threadIdx.x; i < n; i += (size_t)gridDim.x * 256) {
        g_Wq[i] = to_tf32(Wq[i]);
        g_Wk[i] = to_tf32(Wk[i]);
        g_Wv[i] = to_tf32(Wv[i]);
        g_W0[i] = to_tf32(W0[i]);
    }
}

// ---------------- K transpose: g_K [p][n][d] -> g_KT [p][d][n] ----------------
__global__ void __launch_bounds__(256) transpose_k_kernel()
{
    __shared__ float tile[32][33];
    const int p  = blockIdx.z;
    const int nB = blockIdx.x * 32;
    const int dB = blockIdx.y * 32;
    const int tx = threadIdx.x & 31;
    const int ty = threadIdx.x >> 5;
    const float* src = g_K  + (size_t)p * SEQ * DK;
    float*       dst = g_KT + (size_t)p * DK * SEQ;
#pragma unroll
    for (int j = 0; j < 4; j++)
        tile[ty + j * 8][tx] = src[(size_t)(nB + ty + j * 8) * DK + dB + tx];
    __syncthreads();
#pragma unroll
    for (int j = 0; j < 4; j++)
        dst[(size_t)(dB + ty + j * 8) * SEQ + nB + tx] = tile[tx][ty + j * 8];
}

// ---------------- rowsum reduce: g_pr (16 partials/row) -> g_inv --------------
__global__ void __launch_bounds__(256) rowsum_reduce_kernel()
{
    const int idx = blockIdx.x * 256 + threadIdx.x;     // < 24*2048
    const int p   = idx >> 11;
    const int row = idx & 2047;
    float s = 0.0f;
#pragma unroll
    for (int by = 0; by < 16; by++)
        s += g_pr[((size_t)p * 16 + by) * SEQ + row];
    g_inv[idx] = 1.0f / s;
}

// ---------------- stage kernels ----------------------------------------------
// 1) QKV projections: grid (SEQ/128, DK/128, BATCH*9)
__global__ void __launch_bounds__(128, 2) qkv_kernel(
    const float* __restrict__ bq, const float* __restrict__ bk,
    const float* __restrict__ bv)
{
    const int z = blockIdx.z;
    const int b = z / 9, r = z % 9;
    const int mat = r / 3, h = r % 3;
    const float* A    = g_x + (size_t)b * SEQ * EMB;
    const float* W    = (mat == 0 ? g_Wq : (mat == 1 ? g_Wk : g_Wv)) + (size_t)h * EMB * DK;
    const float* bias = (mat == 0 ? bq : (mat == 1 ? bk : bv)) + h * DK;
    float* C = (mat == 0 ? g_Q : (mat == 1 ? g_K : g_V)) + (size_t)(b * NHEAD + h) * SEQ * DK;
    mma_gemm<1>(A, EMB, W, DK, C, DK, EMB, 1.0f, bias, nullptr, nullptr);
}

// 2) P = tf32(exp(Q@KT/16 - 8)) + partial rowsums: grid (SEQ/128, SEQ/128, B*H)
__global__ void __launch_bounds__(128, 2) scores_kernel()
{
    const int p = blockIdx.z;
    const float* A = g_Q  + (size_t)p * SEQ * DK;
    const float* B = g_KT + (size_t)p * DK * SEQ;
    float* C  = g_S  + (size_t)p * SEQ * SEQ;
    float* pr = g_pr + ((size_t)p * 16 + blockIdx.y) * SEQ;
    mma_gemm<2>(A, DK, B, SEQ, C, SEQ, DK, 0.0625f, nullptr, pr, nullptr);
}

// 3) context = (P @ V) * inv[row] into concat layout: grid (SEQ/128, DV/128, B*H)
__global__ void __launch_bounds__(128, 2) av_kernel()
{
    const int p = blockIdx.z;
    const int b = p / NHEAD, h = p % NHEAD;
    const float* A = g_S + (size_t)p * SEQ * SEQ;
    const float* B = g_V + (size_t)p * SEQ * DV;
    float* C = g_C + (size_t)b * SEQ * (NHEAD * DV) + h * DV;
    mma_gemm<3>(A, SEQ, B, DV, C, NHEAD * DV, SEQ, 1.0f, nullptr, nullptr,
                g_inv + (size_t)p * SEQ);
}

// 4) output projection: grid (B*SEQ/128, EMB/128)
__global__ void __launch_bounds__(128, 2) proj_kernel(
    const float* __restrict__ b0, float* __restrict__ out)
{
    mma_gemm<0>(g_C, NHEAD * DV, g_W0, EMB, out, EMB, NHEAD * DV, 1.0f, b0,
                nullptr, nullptr);
}

// ---------------- launch ------------------------------------------------------
extern "C" void kernel_launch(void* const* d_in, const int* in_sizes, int n_in,
                              void* d_out, int out_size)
{
    const float* x  = (const float*)d_in[0];
    const float* Wq = (const float*)d_in[1];
    const float* bq = (const float*)d_in[2];
    const float* Wk = (const float*)d_in[3];
    const float* bk = (const float*)d_in[4];
    const float* Wv = (const float*)d_in[5];
    const float* bv = (const float*)d_in[6];
    const float* W0 = (const float*)d_in[7];
    const float* b0 = (const float*)d_in[8];
    float* out = (float*)d_out;

    static bool attr_done = false;
    if (!attr_done) {
        cudaFuncSetAttribute(qkv_kernel,    cudaFuncAttributeMaxDynamicSharedMemorySize, SMEM_BYTES);
        cudaFuncSetAttribute(scores_kernel, cudaFuncAttributeMaxDynamicSharedMemorySize, SMEM_BYTES);
        cudaFuncSetAttribute(av_kernel,     cudaFuncAttributeMaxDynamicSharedMemorySize, SMEM_BYTES);
        cudaFuncSetAttribute(proj_kernel,   cudaFuncAttributeMaxDynamicSharedMemorySize, SMEM_BYTES);
        attr_done = true;
    }

    round_x_kernel<<<2048, 256>>>(x);
    round_w_kernel<<<512, 256>>>(Wq, Wk, Wv, W0);

    dim3 g1(SEQ / 128, DK / 128, BATCH * 9);
    qkv_kernel<<<g1, 128, SMEM_BYTES>>>(bq, bk, bv);

    dim3 gt(SEQ / 32, DK / 32, BATCH * NHEAD);
    transpose_k_kernel<<<gt, 256>>>();

    dim3 g2(SEQ / 128, SEQ / 128, BATCH * NHEAD);
    scores_kernel<<<g2, 128, SMEM_BYTES>>>();

    rowsum_reduce_kernel<<<(BATCH * NHEAD * SEQ) / 256, 256>>>();

    dim3 g4(SEQ / 128, DV / 128, BATCH * NHEAD);
    av_kernel<<<g4, 128, SMEM_BYTES>>>();

    dim3 g5(BATCH * SEQ / 128, EMB / 128);
    proj_kernel<<<g5, 128, SMEM_BYTES>>>(b0, out);
}